// round 1
// baseline (speedup 1.0000x reference)
#include <cuda_runtime.h>

#define Bsz 4
#define Cin 64
#define OUTC 64
#define H 256
#define W 256
#define HW (H*W)

// Scratch (device globals — no allocation allowed)
__device__ float g_offs[(size_t)Bsz * 18 * HW];   // offset conv output
__device__ float g_wT[9 * Cin * OUTC];            // w_def transposed to [k][c][o]

// ---------------------------------------------------------------------------
// Kernel 0: transpose w_def [o][c][ki][kj] -> g_wT[k][c][o]
// ---------------------------------------------------------------------------
__global__ void transpose_wdef_kernel(const float* __restrict__ w_def) {
    int idx = blockIdx.x * 256 + threadIdx.x;           // 0 .. 36863
    if (idx >= OUTC * Cin * 9) return;
    int o = idx / (Cin * 9);
    int rem = idx - o * (Cin * 9);
    int c = rem / 9;
    int k = rem - c * 9;
    g_wT[(k * Cin + c) * OUTC + o] = w_def[idx];
}

// ---------------------------------------------------------------------------
// Kernel 1: offset conv  offs[b][18][h][w] = conv3x3(x, w_off) + b_off
// One block per (b,h) row, 256 threads = 256 w positions.
// ---------------------------------------------------------------------------
__global__ void __launch_bounds__(256) offsets_kernel(
    const float* __restrict__ x,
    const float* __restrict__ w_off,
    const float* __restrict__ b_off)
{
    // smem weights: [c][tap][j] padded to 20 floats per (c,tap) for float4 reads
    __shared__ float wA[Cin * 9 * 20];

    int tid = threadIdx.x;
    // cooperative load + transpose of w_off [j][c][tap] -> wA[(c*9+tap)*20 + j]
    for (int i = tid; i < Cin * 9 * 18; i += 256) {
        int j = i % 18;
        int ct = i / 18;                  // ct = c*9 + tap
        wA[ct * 20 + j] = w_off[j * (Cin * 9) + ct];
    }
    for (int i = tid; i < Cin * 9; i += 256) {
        wA[i * 20 + 18] = 0.f;
        wA[i * 20 + 19] = 0.f;
    }
    __syncthreads();

    int w = tid;
    int h = blockIdx.x % H;
    int b = blockIdx.x / H;

    float acc[18];
#pragma unroll
    for (int j = 0; j < 18; j++) acc[j] = b_off[j];

    const float* xb = x + (size_t)b * Cin * HW;
    bool hok[3] = { h > 0, true, h < H - 1 };
    bool wok[3] = { w > 0, true, w < W - 1 };

    for (int c = 0; c < Cin; c++) {
        const float* xc = xb + c * HW + h * W + w;
        float v[9];
#pragma unroll
        for (int dy = 0; dy < 3; dy++) {
#pragma unroll
            for (int dx = 0; dx < 3; dx++) {
                int t = dy * 3 + dx;
                v[t] = (hok[dy] && wok[dx]) ? xc[(dy - 1) * W + (dx - 1)] : 0.f;
            }
        }
#pragma unroll
        for (int t = 0; t < 9; t++) {
            float vt = v[t];
            const float* wp = &wA[(c * 9 + t) * 20];
            float4 w0 = *(const float4*)(wp);
            float4 w1 = *(const float4*)(wp + 4);
            float4 w2 = *(const float4*)(wp + 8);
            float4 w3 = *(const float4*)(wp + 12);
            float2 w4 = *(const float2*)(wp + 16);
            acc[0]  += vt * w0.x;  acc[1]  += vt * w0.y;
            acc[2]  += vt * w0.z;  acc[3]  += vt * w0.w;
            acc[4]  += vt * w1.x;  acc[5]  += vt * w1.y;
            acc[6]  += vt * w1.z;  acc[7]  += vt * w1.w;
            acc[8]  += vt * w2.x;  acc[9]  += vt * w2.y;
            acc[10] += vt * w2.z;  acc[11] += vt * w2.w;
            acc[12] += vt * w3.x;  acc[13] += vt * w3.y;
            acc[14] += vt * w3.z;  acc[15] += vt * w3.w;
            acc[16] += vt * w4.x;  acc[17] += vt * w4.y;
        }
    }

    float* ob = g_offs + ((size_t)b * 18) * HW + h * W + w;
#pragma unroll
    for (int j = 0; j < 18; j++) ob[(size_t)j * HW] = acc[j];
}

// ---------------------------------------------------------------------------
// Kernel 2: deformable sampling + 9x (64x64) channel GEMM
// Block = 64 consecutive pixels of one row. 256 threads.
// Per k: stage weights [c][o] + bilinear samples [c][px] in smem,
// then each thread accumulates a 4oc x 4px register tile over c.
// ---------------------------------------------------------------------------
struct __align__(16) SampleParam { int y0; int x0; float ly; float lx; };

__global__ void __launch_bounds__(256) deform_kernel(
    const float* __restrict__ x,
    const float* __restrict__ b_def,
    float* __restrict__ out)
{
    __shared__ SampleParam sp[9][64];    // 9216 B
    __shared__ float ssm[Cin][64];       // 16 KB  sampled[c][px]
    __shared__ float wsm[Cin][OUTC];     // 16 KB  weights[c][o] for current k

    int tid = threadIdx.x;
    int bx = blockIdx.x;
    int wt = (bx & 3) << 6;              // tile start in w
    int h = (bx >> 2) & (H - 1);
    int b = bx >> 10;

    const float* xb = x + (size_t)b * Cin * HW;
    const float* offb = g_offs + (size_t)b * 18 * HW + h * W + wt;

    // ---- per-(px,k) sampling params ----
    for (int i = tid; i < 576; i += 256) {
        int k = i >> 6;
        int px = i & 63;
        float offy = offb[(size_t)(2 * k) * HW + px];
        float offx = offb[(size_t)(2 * k + 1) * HW + px];
        float ys = (float)(h + (k / 3) - 1) + offy;
        float xs = (float)(wt + px + (k % 3) - 1) + offx;
        float y0f = floorf(ys);
        float x0f = floorf(xs);
        SampleParam p;
        p.y0 = (int)y0f;
        p.x0 = (int)x0f;
        p.ly = ys - y0f;
        p.lx = xs - x0f;
        sp[k][px] = p;
    }

    float acc[4][4];
#pragma unroll
    for (int a = 0; a < 4; a++)
#pragma unroll
        for (int d = 0; d < 4; d++) acc[a][d] = 0.f;

    int pxg = (tid & 15) << 2;   // pixel group base (0..60)
    int ocg = (tid >> 4) << 2;   // out-channel group base (0..60)
    int spx = tid & 63;          // sampling pixel
    int scb = tid >> 6;          // sampling channel base offset (0..3)

    for (int k = 0; k < 9; k++) {
        __syncthreads();  // sp ready (k=0); ssm/wsm free of prior readers (k>0)

        // stage weights for this k
        {
            const float4* src = (const float4*)(g_wT + (size_t)k * Cin * OUTC);
            float4* dst = (float4*)&wsm[0][0];
            for (int i = tid; i < Cin * OUTC / 4; i += 256) dst[i] = src[i];
        }

        // bilinear sampling: each thread fills 16 (c, px=spx) entries
        SampleParam p = sp[k][spx];
        float ly = p.ly, lx = p.lx;
        float hy = 1.f - ly, hx = 1.f - lx;
        float w00 = hy * hx, w01 = hy * lx, w10 = ly * hx, w11 = ly * lx;
        int y0 = p.y0, x0 = p.x0;
        bool y0k = ((unsigned)y0 < (unsigned)H);
        bool y1k = ((unsigned)(y0 + 1) < (unsigned)H);
        bool x0k = ((unsigned)x0 < (unsigned)W);
        bool x1k = ((unsigned)(x0 + 1) < (unsigned)W);
        const float* rbase = xb + (ptrdiff_t)y0 * W + x0;
#pragma unroll
        for (int i = 0; i < 16; i++) {
            int c = (i << 2) + scb;
            const float* r = rbase + c * HW;
            float v00 = (y0k && x0k) ? r[0]     : 0.f;
            float v01 = (y0k && x1k) ? r[1]     : 0.f;
            float v10 = (y1k && x0k) ? r[W]     : 0.f;
            float v11 = (y1k && x1k) ? r[W + 1] : 0.f;
            ssm[c][spx] = w00 * v00 + w01 * v01 + w10 * v10 + w11 * v11;
        }
        __syncthreads();

        // register-tiled GEMM: acc[4oc][4px] += wsm[c][ocg..] * ssm[c][pxg..]
#pragma unroll 8
        for (int c = 0; c < Cin; c++) {
            float4 s = *(const float4*)&ssm[c][pxg];
            float4 wv = *(const float4*)&wsm[c][ocg];
            acc[0][0] += wv.x * s.x; acc[0][1] += wv.x * s.y;
            acc[0][2] += wv.x * s.z; acc[0][3] += wv.x * s.w;
            acc[1][0] += wv.y * s.x; acc[1][1] += wv.y * s.y;
            acc[1][2] += wv.y * s.z; acc[1][3] += wv.y * s.w;
            acc[2][0] += wv.z * s.x; acc[2][1] += wv.z * s.y;
            acc[2][2] += wv.z * s.z; acc[2][3] += wv.z * s.w;
            acc[3][0] += wv.w * s.x; acc[3][1] += wv.w * s.y;
            acc[3][2] += wv.w * s.z; acc[3][3] += wv.w * s.w;
        }
    }

    // epilogue: add bias, write float4 per out-channel
    float4 bd = *(const float4*)&b_def[ocg];
    float bda[4] = { bd.x, bd.y, bd.z, bd.w };
    float* ob = out + ((size_t)(b * OUTC + ocg) * H + h) * W + wt + pxg;
#pragma unroll
    for (int oi = 0; oi < 4; oi++) {
        float4 r;
        r.x = acc[oi][0] + bda[oi];
        r.y = acc[oi][1] + bda[oi];
        r.z = acc[oi][2] + bda[oi];
        r.w = acc[oi][3] + bda[oi];
        *(float4*)(ob + (size_t)oi * HW) = r;
    }
}

// ---------------------------------------------------------------------------
extern "C" void kernel_launch(void* const* d_in, const int* in_sizes, int n_in,
                              void* d_out, int out_size)
{
    const float* x     = (const float*)d_in[0];
    const float* w_off = (const float*)d_in[1];
    const float* b_off = (const float*)d_in[2];
    const float* w_def = (const float*)d_in[3];
    const float* b_def = (const float*)d_in[4];
    float* out = (float*)d_out;

    transpose_wdef_kernel<<<(OUTC * Cin * 9 + 255) / 256, 256>>>(w_def);
    offsets_kernel<<<Bsz * H, 256>>>(x, w_off, b_off);
    deform_kernel<<<Bsz * H * (W / 64), 256>>>(x, b_def, out);
}

// round 2
// speedup vs baseline: 1.2114x; 1.2114x over previous
#include <cuda_runtime.h>
#include <cstdint>

#define Bsz 4
#define Cin 64
#define OUTC 64
#define H 256
#define W 256
#define HW (H*W)

#define MTILE 128          // pixels per CTA
#define SSTRIDE 136        // ssm row stride (128 + 8 pad) -> conflict-free frags
#define WSTRIDE 72         // wsm row stride (64 + 8 pad)

// Scratch (device globals — no allocation allowed)
__device__ float g_offs[(size_t)Bsz * 18 * HW];   // offset conv output (fp32 exact)
__device__ float g_wT[9 * Cin * OUTC];            // w_def -> [k][c][o], tf32-rounded bits

// ---------------------------------------------------------------------------
// tf32 helpers
// ---------------------------------------------------------------------------
__device__ __forceinline__ uint32_t f32_to_tf32(float v) {
    uint32_t t;
    asm("cvt.rna.tf32.f32 %0, %1;" : "=r"(t) : "f"(v));
    return t;
}

__device__ __forceinline__ void mma_tf32(float* d, const uint32_t* a, const uint32_t* b) {
    asm volatile(
        "mma.sync.aligned.m16n8k8.row.col.f32.tf32.tf32.f32 "
        "{%0,%1,%2,%3}, {%4,%5,%6,%7}, {%8,%9}, {%0,%1,%2,%3};"
        : "+f"(d[0]), "+f"(d[1]), "+f"(d[2]), "+f"(d[3])
        : "r"(a[0]), "r"(a[1]), "r"(a[2]), "r"(a[3]),
          "r"(b[0]), "r"(b[1]));
}

// ---------------------------------------------------------------------------
// Kernel 0: transpose w_def [o][c][ki][kj] -> g_wT[k][c][o], rounded to tf32
// ---------------------------------------------------------------------------
__global__ void transpose_wdef_kernel(const float* __restrict__ w_def) {
    int idx = blockIdx.x * 256 + threadIdx.x;
    if (idx >= OUTC * Cin * 9) return;
    int o = idx / (Cin * 9);
    int rem = idx - o * (Cin * 9);
    int c = rem / 9;
    int k = rem - c * 9;
    g_wT[(k * Cin + c) * OUTC + o] = __uint_as_float(f32_to_tf32(w_def[idx]));
}

// ---------------------------------------------------------------------------
// Kernel 1: offset conv (exact fp32 — positions must not lose precision)
// ---------------------------------------------------------------------------
__global__ void __launch_bounds__(256) offsets_kernel(
    const float* __restrict__ x,
    const float* __restrict__ w_off,
    const float* __restrict__ b_off)
{
    __shared__ float wA[Cin * 9 * 20];

    int tid = threadIdx.x;
    for (int i = tid; i < Cin * 9 * 18; i += 256) {
        int j = i % 18;
        int ct = i / 18;
        wA[ct * 20 + j] = w_off[j * (Cin * 9) + ct];
    }
    for (int i = tid; i < Cin * 9; i += 256) {
        wA[i * 20 + 18] = 0.f;
        wA[i * 20 + 19] = 0.f;
    }
    __syncthreads();

    int w = tid;
    int h = blockIdx.x % H;
    int b = blockIdx.x / H;

    float acc[18];
#pragma unroll
    for (int j = 0; j < 18; j++) acc[j] = b_off[j];

    const float* xb = x + (size_t)b * Cin * HW;
    bool hok[3] = { h > 0, true, h < H - 1 };
    bool wok[3] = { w > 0, true, w < W - 1 };

    for (int c = 0; c < Cin; c++) {
        const float* xc = xb + c * HW + h * W + w;
        float v[9];
#pragma unroll
        for (int dy = 0; dy < 3; dy++)
#pragma unroll
            for (int dx = 0; dx < 3; dx++) {
                int t = dy * 3 + dx;
                v[t] = (hok[dy] && wok[dx]) ? xc[(dy - 1) * W + (dx - 1)] : 0.f;
            }
#pragma unroll
        for (int t = 0; t < 9; t++) {
            float vt = v[t];
            const float* wp = &wA[(c * 9 + t) * 20];
            float4 w0 = *(const float4*)(wp);
            float4 w1 = *(const float4*)(wp + 4);
            float4 w2 = *(const float4*)(wp + 8);
            float4 w3 = *(const float4*)(wp + 12);
            float2 w4 = *(const float2*)(wp + 16);
            acc[0]  += vt * w0.x;  acc[1]  += vt * w0.y;
            acc[2]  += vt * w0.z;  acc[3]  += vt * w0.w;
            acc[4]  += vt * w1.x;  acc[5]  += vt * w1.y;
            acc[6]  += vt * w1.z;  acc[7]  += vt * w1.w;
            acc[8]  += vt * w2.x;  acc[9]  += vt * w2.y;
            acc[10] += vt * w2.z;  acc[11] += vt * w2.w;
            acc[12] += vt * w3.x;  acc[13] += vt * w3.y;
            acc[14] += vt * w3.z;  acc[15] += vt * w3.w;
            acc[16] += vt * w4.x;  acc[17] += vt * w4.y;
        }
    }

    float* ob = g_offs + ((size_t)b * 18) * HW + h * W + w;
#pragma unroll
    for (int j = 0; j < 18; j++) ob[(size_t)j * HW] = acc[j];
}

// ---------------------------------------------------------------------------
// Kernel 2: deform sampling + tf32 tensor-core GEMM
// CTA: 128 px (half row) x 64 oc. 256 threads = 8 warps.
// Warp tile: 32px x 32oc  (2 m16 x 4 n8 mma tiles).
// Per tap k: stage wsm[64c][64o] + sampled ssm[64c][128px] (tf32 bits) in smem,
// then 8 k-steps of m16n8k8 MMA accumulating in registers.
// ---------------------------------------------------------------------------
struct __align__(16) SampleParam { int y0; int x0; float ly; float lx; };

// dynamic smem: ssm[64*136] u32 | wsm[64*72] u32 | sp[9*128] (16B)
#define SSM_U32   (Cin * SSTRIDE)
#define WSM_U32   (Cin * WSTRIDE)
#define DSMEM_BYTES ((SSM_U32 + WSM_U32) * 4 + 9 * MTILE * 16)

__global__ void __launch_bounds__(256) deform_kernel(
    const float* __restrict__ x,
    const float* __restrict__ b_def,
    float* __restrict__ out)
{
    extern __shared__ uint32_t dsm[];
    uint32_t* ssm = dsm;                       // [c][px] stride 136
    uint32_t* wsm = dsm + SSM_U32;             // [c][o]  stride 72
    SampleParam* sp = (SampleParam*)(dsm + SSM_U32 + WSM_U32);  // [k][px]

    int tid = threadIdx.x;
    int bx = blockIdx.x;
    int wt = (bx & 1) << 7;            // 0 or 128
    int h = (bx >> 1) & (H - 1);
    int b = bx >> 9;

    const float* xb = x + (size_t)b * Cin * HW;
    const float* offb = g_offs + (size_t)b * 18 * HW + h * W + wt;

    // ---- sampling params for all 9 taps x 128 px ----
    for (int i = tid; i < 9 * MTILE; i += 256) {
        int k = i >> 7;
        int px = i & (MTILE - 1);
        float offy = offb[(size_t)(2 * k) * HW + px];
        float offx = offb[(size_t)(2 * k + 1) * HW + px];
        float ys = (float)(h + (k / 3) - 1) + offy;
        float xs = (float)(wt + px + (k % 3) - 1) + offx;
        float y0f = floorf(ys);
        float x0f = floorf(xs);
        SampleParam p;
        p.y0 = (int)y0f;
        p.x0 = (int)x0f;
        p.ly = ys - y0f;
        p.lx = xs - x0f;
        sp[k * MTILE + px] = p;
    }

    // warp tiling
    int lane = tid & 31;
    int wid = tid >> 5;
    int warp_m = (wid & 3) << 5;       // 0,32,64,96
    int warp_n = (wid >> 2) << 5;      // 0,32
    int r = lane & 3;                  // threadID_in_group
    int g = lane >> 2;                 // groupID

    float acc[2][4][4];
#pragma unroll
    for (int mi = 0; mi < 2; mi++)
#pragma unroll
        for (int ni = 0; ni < 4; ni++)
#pragma unroll
            for (int q = 0; q < 4; q++) acc[mi][ni][q] = 0.f;

    // sampling thread mapping
    int spx = tid & (MTILE - 1);       // pixel
    int scg = (tid >> 7) << 5;         // channel base: 0 or 32

    for (int k = 0; k < 9; k++) {
        __syncthreads();   // sp ready (k=0); ssm/wsm free of readers (k>0)

        // stage tf32 weights for this tap (pad stride 64->72)
        {
            const float4* src = (const float4*)(g_wT + (size_t)k * Cin * OUTC);
            for (int i = tid; i < Cin * OUTC / 4; i += 256) {
                int c = i >> 4;
                int q = i & 15;
                ((float4*)(wsm + c * WSTRIDE))[q] = src[i];
            }
        }

        // bilinear sampling: thread fills 32 channels at px=spx
        SampleParam p = sp[k * MTILE + spx];
        float ly = p.ly, lx = p.lx;
        float hy = 1.f - ly, hx = 1.f - lx;
        float w00 = hy * hx, w01 = hy * lx, w10 = ly * hx, w11 = ly * lx;
        int y0 = p.y0, x0 = p.x0;
        bool y0k = ((unsigned)y0 < (unsigned)H);
        bool y1k = ((unsigned)(y0 + 1) < (unsigned)H);
        bool x0k = ((unsigned)x0 < (unsigned)W);
        bool x1k = ((unsigned)(x0 + 1) < (unsigned)W);
        const float* rbase = xb + (ptrdiff_t)y0 * W + x0 + (ptrdiff_t)scg * HW;
        uint32_t* sdst = ssm + (size_t)scg * SSTRIDE + spx;
#pragma unroll 8
        for (int i = 0; i < 32; i++) {
            const float* rp = rbase + (ptrdiff_t)i * HW;
            float v00 = (y0k && x0k) ? rp[0]     : 0.f;
            float v01 = (y0k && x1k) ? rp[1]     : 0.f;
            float v10 = (y1k && x0k) ? rp[W]     : 0.f;
            float v11 = (y1k && x1k) ? rp[W + 1] : 0.f;
            float val = w00 * v00 + w01 * v01 + w10 * v10 + w11 * v11;
            sdst[(size_t)i * SSTRIDE] = f32_to_tf32(val);
        }
        __syncthreads();

        // MMA: 8 k-steps of m16n8k8
#pragma unroll
        for (int kk = 0; kk < 8; kk++) {
            int k0 = kk << 3;
            uint32_t a[2][4];
            const uint32_t* ar = ssm + (k0 + r) * SSTRIDE + warp_m + g;
#pragma unroll
            for (int mi = 0; mi < 2; mi++) {
                a[mi][0] = ar[mi * 16];
                a[mi][1] = ar[mi * 16 + 8];
                a[mi][2] = ar[mi * 16 + 4 * SSTRIDE];
                a[mi][3] = ar[mi * 16 + 8 + 4 * SSTRIDE];
            }
            uint32_t bb[4][2];
            const uint32_t* br = wsm + (k0 + r) * WSTRIDE + warp_n + g;
#pragma unroll
            for (int ni = 0; ni < 4; ni++) {
                bb[ni][0] = br[ni * 8];
                bb[ni][1] = br[ni * 8 + 4 * WSTRIDE];
            }
#pragma unroll
            for (int mi = 0; mi < 2; mi++)
#pragma unroll
                for (int ni = 0; ni < 4; ni++)
                    mma_tf32(acc[mi][ni], a[mi], bb[ni]);
        }
    }

    // ---- epilogue: bias + direct stores ----
#pragma unroll
    for (int ni = 0; ni < 4; ni++) {
        int o = warp_n + ni * 8 + 2 * r;
        float bo0 = b_def[o];
        float bo1 = b_def[o + 1];
        float* ob0 = out + ((size_t)(b * OUTC + o)) * HW + h * W + wt;
        float* ob1 = ob0 + HW;
#pragma unroll
        for (int mi = 0; mi < 2; mi++) {
            int px = warp_m + mi * 16 + g;
            ob0[px]     = acc[mi][ni][0] + bo0;
            ob1[px]     = acc[mi][ni][1] + bo1;
            ob0[px + 8] = acc[mi][ni][2] + bo0;
            ob1[px + 8] = acc[mi][ni][3] + bo1;
        }
    }
}

// ---------------------------------------------------------------------------
extern "C" void kernel_launch(void* const* d_in, const int* in_sizes, int n_in,
                              void* d_out, int out_size)
{
    const float* x     = (const float*)d_in[0];
    const float* w_off = (const float*)d_in[1];
    const float* b_off = (const float*)d_in[2];
    const float* w_def = (const float*)d_in[3];
    const float* b_def = (const float*)d_in[4];
    float* out = (float*)d_out;

    cudaFuncSetAttribute(deform_kernel,
                         cudaFuncAttributeMaxDynamicSharedMemorySize, DSMEM_BYTES);

    transpose_wdef_kernel<<<(OUTC * Cin * 9 + 255) / 256, 256>>>(w_def);
    offsets_kernel<<<Bsz * H, 256>>>(x, w_off, b_off);
    deform_kernel<<<Bsz * H * (W / MTILE), 256, DSMEM_BYTES>>>(x, b_def, out);
}

// round 3
// speedup vs baseline: 1.7129x; 1.4140x over previous
#include <cuda_runtime.h>
#include <cstdint>

#define Bsz 4
#define Cin 64
#define OUTC 64
#define H 256
#define W 256
#define HW (H*W)

#define MTILE 128          // pixels per CTA (half row)
#define SSTRIDE 68         // ssm row stride in floats: [px][c], 64+4 pad
#define WSTRIDE 72         // wsm row stride: [c][o], 64+8 pad

// Scratch (device globals — no allocation allowed)
__device__ float g_offs[(size_t)Bsz * 18 * HW];        // offset conv output (fp32)
__device__ float g_wT[9 * Cin * OUTC];                 // w_def -> [k][c][o] (tf32 bits)
__device__ float g_xt[(size_t)Bsz * HW * Cin];         // x transposed to NHWC (64MB)

// ---------------------------------------------------------------------------
// tf32 helpers
// ---------------------------------------------------------------------------
__device__ __forceinline__ uint32_t f32_to_tf32(float v) {
    uint32_t t;
    asm("cvt.rna.tf32.f32 %0, %1;" : "=r"(t) : "f"(v));
    return t;
}

__device__ __forceinline__ void mma_tf32(float* d, const uint32_t* a, const uint32_t* b) {
    asm volatile(
        "mma.sync.aligned.m16n8k8.row.col.f32.tf32.tf32.f32 "
        "{%0,%1,%2,%3}, {%4,%5,%6,%7}, {%8,%9}, {%0,%1,%2,%3};"
        : "+f"(d[0]), "+f"(d[1]), "+f"(d[2]), "+f"(d[3])
        : "r"(a[0]), "r"(a[1]), "r"(a[2]), "r"(a[3]),
          "r"(b[0]), "r"(b[1]));
}

// ---------------------------------------------------------------------------
// Kernel 0a: transpose w_def [o][c][ki][kj] -> g_wT[k][c][o], tf32-rounded
// ---------------------------------------------------------------------------
__global__ void transpose_wdef_kernel(const float* __restrict__ w_def) {
    int idx = blockIdx.x * 256 + threadIdx.x;
    if (idx >= OUTC * Cin * 9) return;
    int o = idx / (Cin * 9);
    int rem = idx - o * (Cin * 9);
    int c = rem / 9;
    int k = rem - c * 9;
    g_wT[(k * Cin + c) * OUTC + o] = __uint_as_float(f32_to_tf32(w_def[idx]));
}

// ---------------------------------------------------------------------------
// Kernel 0b: transpose x NCHW -> NHWC (g_xt). Block: one (b,h), 32-w tile.
// ---------------------------------------------------------------------------
__global__ void __launch_bounds__(256) transpose_x_kernel(const float* __restrict__ x) {
    __shared__ float t[Cin][33];
    int tid = threadIdx.x;
    int bx = blockIdx.x;
    int wt = (bx & 7) << 5;            // 32-px tile
    int h = (bx >> 3) & (H - 1);
    int b = bx >> 11;

    const float* xb = x + (size_t)b * Cin * HW + h * W + wt;
#pragma unroll
    for (int it = 0; it < 8; it++) {
        int c = it * 8 + (tid >> 5);
        int w = tid & 31;
        t[c][w] = xb[(size_t)c * HW + w];
    }
    __syncthreads();
    float* xo = g_xt + ((size_t)(b * H + h) * W + wt) * Cin;
#pragma unroll
    for (int it = 0; it < 8; it++) {
        int w = it * 4 + (tid >> 6);
        int c = tid & 63;
        xo[(size_t)w * Cin + c] = t[c][w];
    }
}

// ---------------------------------------------------------------------------
// Kernel 1: offset conv (exact fp32, reads original NCHW x)
// ---------------------------------------------------------------------------
__global__ void __launch_bounds__(256) offsets_kernel(
    const float* __restrict__ x,
    const float* __restrict__ w_off,
    const float* __restrict__ b_off)
{
    __shared__ float wA[Cin * 9 * 20];

    int tid = threadIdx.x;
    for (int i = tid; i < Cin * 9 * 18; i += 256) {
        int j = i % 18;
        int ct = i / 18;
        wA[ct * 20 + j] = w_off[j * (Cin * 9) + ct];
    }
    for (int i = tid; i < Cin * 9; i += 256) {
        wA[i * 20 + 18] = 0.f;
        wA[i * 20 + 19] = 0.f;
    }
    __syncthreads();

    int w = tid;
    int h = blockIdx.x % H;
    int b = blockIdx.x / H;

    float acc[18];
#pragma unroll
    for (int j = 0; j < 18; j++) acc[j] = b_off[j];

    const float* xb = x + (size_t)b * Cin * HW;
    bool hok[3] = { h > 0, true, h < H - 1 };
    bool wok[3] = { w > 0, true, w < W - 1 };

    for (int c = 0; c < Cin; c++) {
        const float* xc = xb + c * HW + h * W + w;
        float v[9];
#pragma unroll
        for (int dy = 0; dy < 3; dy++)
#pragma unroll
            for (int dx = 0; dx < 3; dx++) {
                int t = dy * 3 + dx;
                v[t] = (hok[dy] && wok[dx]) ? xc[(dy - 1) * W + (dx - 1)] : 0.f;
            }
#pragma unroll
        for (int t = 0; t < 9; t++) {
            float vt = v[t];
            const float* wp = &wA[(c * 9 + t) * 20];
            float4 w0 = *(const float4*)(wp);
            float4 w1 = *(const float4*)(wp + 4);
            float4 w2 = *(const float4*)(wp + 8);
            float4 w3 = *(const float4*)(wp + 12);
            float2 w4 = *(const float2*)(wp + 16);
            acc[0]  += vt * w0.x;  acc[1]  += vt * w0.y;
            acc[2]  += vt * w0.z;  acc[3]  += vt * w0.w;
            acc[4]  += vt * w1.x;  acc[5]  += vt * w1.y;
            acc[6]  += vt * w1.z;  acc[7]  += vt * w1.w;
            acc[8]  += vt * w2.x;  acc[9]  += vt * w2.y;
            acc[10] += vt * w2.z;  acc[11] += vt * w2.w;
            acc[12] += vt * w3.x;  acc[13] += vt * w3.y;
            acc[14] += vt * w3.z;  acc[15] += vt * w3.w;
            acc[16] += vt * w4.x;  acc[17] += vt * w4.y;
        }
    }

    float* ob = g_offs + ((size_t)b * 18) * HW + h * W + w;
#pragma unroll
    for (int j = 0; j < 18; j++) ob[(size_t)j * HW] = acc[j];
}

// ---------------------------------------------------------------------------
// Kernel 2: deform sampling (NHWC, coalesced) + tf32 tensor-core GEMM
// CTA: 128 px x 64 oc, 256 threads = 8 warps. Warp MMA tile: 32px x 32oc.
// Sampling: warp w handles samples px = 16w..16w+15; per sample each lane
// loads float2 (2 channels) per corner — fully coalesced 256B per corner.
// ---------------------------------------------------------------------------
struct __align__(16) SampleParam { int y0; int x0; float ly; float lx; };

#define SSM_U32 (MTILE * SSTRIDE)
#define WSM_U32 (Cin * WSTRIDE)
#define DSMEM_BYTES ((SSM_U32 + WSM_U32) * 4 + 9 * MTILE * 16)

__global__ void __launch_bounds__(256) deform_kernel(
    const float* __restrict__ b_def,
    float* __restrict__ out)
{
    extern __shared__ uint32_t dsm[];
    uint32_t* ssm = dsm;                        // [px][c] stride 68
    uint32_t* wsm = dsm + SSM_U32;              // [c][o]  stride 72
    SampleParam* sp = (SampleParam*)(dsm + SSM_U32 + WSM_U32);   // [k][px]

    int tid = threadIdx.x;
    int bx = blockIdx.x;
    int wt = (bx & 1) << 7;             // 0 or 128
    int h = (bx >> 1) & (H - 1);
    int b = bx >> 9;

    const float* offb = g_offs + (size_t)b * 18 * HW + h * W + wt;

    // ---- sampling params for all 9 taps x 128 px ----
    for (int i = tid; i < 9 * MTILE; i += 256) {
        int k = i >> 7;
        int px = i & (MTILE - 1);
        float offy = offb[(size_t)(2 * k) * HW + px];
        float offx = offb[(size_t)(2 * k + 1) * HW + px];
        float ys = (float)(h + (k / 3) - 1) + offy;
        float xs = (float)(wt + px + (k % 3) - 1) + offx;
        float y0f = floorf(ys);
        float x0f = floorf(xs);
        SampleParam p;
        p.y0 = (int)y0f;
        p.x0 = (int)x0f;
        p.ly = ys - y0f;
        p.lx = xs - x0f;
        sp[k * MTILE + px] = p;
    }

    int lane = tid & 31;
    int wid = tid >> 5;
    int warp_m = (wid & 3) << 5;        // 0,32,64,96
    int warp_n = (wid >> 2) << 5;       // 0,32
    int r = lane & 3;
    int g = lane >> 2;

    float acc[2][4][4];
#pragma unroll
    for (int mi = 0; mi < 2; mi++)
#pragma unroll
        for (int ni = 0; ni < 4; ni++)
#pragma unroll
            for (int q = 0; q < 4; q++) acc[mi][ni][q] = 0.f;

    const float2* xtb = (const float2*)(g_xt + (size_t)b * HW * Cin) + lane;
    int px0 = wid << 4;                 // 16 samples per warp

    for (int k = 0; k < 9; k++) {
        __syncthreads();   // sp ready (k=0); ssm/wsm free of readers (k>0)

        // stage tf32 weights for this tap (stride 64 -> 72)
        {
            const float4* src = (const float4*)(g_wT + (size_t)k * Cin * OUTC);
            for (int i = tid; i < Cin * OUTC / 4; i += 256) {
                int c = i >> 4;
                int q = i & 15;
                ((float4*)(wsm + c * WSTRIDE))[q] = src[i];
            }
        }

        // coalesced bilinear sampling: warp covers 16 px, lane = 2 channels
#pragma unroll 4
        for (int s = 0; s < 16; s++) {
            int px = px0 + s;
            SampleParam p = sp[k * MTILE + px];
            float hy = 1.f - p.ly, hx = 1.f - p.lx;
            float w00 = hy * hx, w01 = hy * p.lx;
            float w10 = p.ly * hx, w11 = p.ly * p.lx;
            bool y0k = ((unsigned)p.y0 < (unsigned)H);
            bool y1k = ((unsigned)(p.y0 + 1) < (unsigned)H);
            bool x0k = ((unsigned)p.x0 < (unsigned)W);
            bool x1k = ((unsigned)(p.x0 + 1) < (unsigned)W);
            const float2* base = xtb + (ptrdiff_t)(p.y0 * W + p.x0) * (Cin / 2);
            float2 z = make_float2(0.f, 0.f);
            float2 v00 = (y0k && x0k) ? base[0] : z;
            float2 v01 = (y0k && x1k) ? base[Cin / 2] : z;
            float2 v10 = (y1k && x0k) ? base[(ptrdiff_t)W * (Cin / 2)] : z;
            float2 v11 = (y1k && x1k) ? base[(ptrdiff_t)(W + 1) * (Cin / 2)] : z;
            float vx = w00 * v00.x + w01 * v01.x + w10 * v10.x + w11 * v11.x;
            float vy = w00 * v00.y + w01 * v01.y + w10 * v10.y + w11 * v11.y;
            uint2 tv = make_uint2(f32_to_tf32(vx), f32_to_tf32(vy));
            *(uint2*)&ssm[px * SSTRIDE + 2 * lane] = tv;
        }
        __syncthreads();

        // MMA: 8 k-steps of m16n8k8; A from ssm[px][c], B from wsm[c][o]
#pragma unroll
        for (int kk = 0; kk < 8; kk++) {
            int k0 = kk << 3;
            uint32_t a[2][4];
#pragma unroll
            for (int mi = 0; mi < 2; mi++) {
                const uint32_t* ar = ssm + (warp_m + 16 * mi + g) * SSTRIDE + k0 + r;
                a[mi][0] = ar[0];
                a[mi][1] = ar[8 * SSTRIDE];
                a[mi][2] = ar[4];
                a[mi][3] = ar[8 * SSTRIDE + 4];
            }
            uint32_t bb[4][2];
            const uint32_t* br = wsm + (k0 + r) * WSTRIDE + warp_n + g;
#pragma unroll
            for (int ni = 0; ni < 4; ni++) {
                bb[ni][0] = br[ni * 8];
                bb[ni][1] = br[ni * 8 + 4 * WSTRIDE];
            }
#pragma unroll
            for (int mi = 0; mi < 2; mi++)
#pragma unroll
                for (int ni = 0; ni < 4; ni++)
                    mma_tf32(acc[mi][ni], a[mi], bb[ni]);
        }
    }

    // ---- epilogue: bias + direct stores (NCHW out) ----
#pragma unroll
    for (int ni = 0; ni < 4; ni++) {
        int o = warp_n + ni * 8 + 2 * r;
        float bo0 = b_def[o];
        float bo1 = b_def[o + 1];
        float* ob0 = out + ((size_t)(b * OUTC + o)) * HW + h * W + wt;
        float* ob1 = ob0 + HW;
#pragma unroll
        for (int mi = 0; mi < 2; mi++) {
            int px = warp_m + mi * 16 + g;
            ob0[px]     = acc[mi][ni][0] + bo0;
            ob1[px]     = acc[mi][ni][1] + bo1;
            ob0[px + 8] = acc[mi][ni][2] + bo0;
            ob1[px + 8] = acc[mi][ni][3] + bo1;
        }
    }
}

// ---------------------------------------------------------------------------
extern "C" void kernel_launch(void* const* d_in, const int* in_sizes, int n_in,
                              void* d_out, int out_size)
{
    const float* x     = (const float*)d_in[0];
    const float* w_off = (const float*)d_in[1];
    const float* b_off = (const float*)d_in[2];
    const float* w_def = (const float*)d_in[3];
    const float* b_def = (const float*)d_in[4];
    float* out = (float*)d_out;

    cudaFuncSetAttribute(deform_kernel,
                         cudaFuncAttributeMaxDynamicSharedMemorySize, DSMEM_BYTES);

    transpose_wdef_kernel<<<(OUTC * Cin * 9 + 255) / 256, 256>>>(w_def);
    transpose_x_kernel<<<Bsz * H * (W / 32), 256>>>(x);
    offsets_kernel<<<Bsz * H, 256>>>(x, w_off, b_off);
    deform_kernel<<<Bsz * H * (W / MTILE), 256, DSMEM_BYTES>>>(b_def, out);
}

// round 4
// speedup vs baseline: 1.7527x; 1.0233x over previous
#include <cuda_runtime.h>
#include <cstdint>

#define Bsz 4
#define Cin 64
#define OUTC 64
#define H 256
#define W 256
#define HW (H*W)

#define MTILE 128          // pixels per CTA (half row)
#define SSTRIDE 68         // ssm row stride in floats: [px][c], 64+4 pad
#define WSTRIDE 72         // wsm row stride: [c][o], 64+8 pad

// Scratch (device globals — no allocation allowed)
__device__ float g_offs[(size_t)Bsz * 18 * HW];        // offset conv output (fp32)
__device__ float g_wT[9 * Cin * OUTC];                 // w_def -> [k][c][o] (tf32 bits)
__device__ float g_xt[(size_t)Bsz * HW * Cin];         // x transposed to NHWC (64MB)

// ---------------------------------------------------------------------------
// tf32 / f32x2 helpers
// ---------------------------------------------------------------------------
__device__ __forceinline__ uint32_t f32_to_tf32(float v) {
    uint32_t t;
    asm("cvt.rna.tf32.f32 %0, %1;" : "=r"(t) : "f"(v));
    return t;
}

__device__ __forceinline__ void mma_tf32(float* d, const uint32_t* a, const uint32_t* b) {
    asm volatile(
        "mma.sync.aligned.m16n8k8.row.col.f32.tf32.tf32.f32 "
        "{%0,%1,%2,%3}, {%4,%5,%6,%7}, {%8,%9}, {%0,%1,%2,%3};"
        : "+f"(d[0]), "+f"(d[1]), "+f"(d[2]), "+f"(d[3])
        : "r"(a[0]), "r"(a[1]), "r"(a[2]), "r"(a[3]),
          "r"(b[0]), "r"(b[1]));
}

// packed dual-FMA: d = a*b + d (elementwise on 2 floats) — exact fp32
__device__ __forceinline__ void ffma2(unsigned long long& d,
                                      unsigned long long a,
                                      unsigned long long b) {
    asm("fma.rn.f32x2 %0, %1, %2, %0;" : "+l"(d) : "l"(a), "l"(b));
}

__device__ __forceinline__ unsigned long long bcast2(float v) {
    unsigned long long r;
    asm("mov.b64 %0, {%1, %1};" : "=l"(r) : "f"(v));
    return r;
}

__device__ __forceinline__ void unpack2(unsigned long long v, float& lo, float& hi) {
    asm("mov.b64 {%0, %1}, %2;" : "=f"(lo), "=f"(hi) : "l"(v));
}

// ---------------------------------------------------------------------------
// Kernel 0a: transpose w_def [o][c][ki][kj] -> g_wT[k][c][o], tf32-rounded
// ---------------------------------------------------------------------------
__global__ void transpose_wdef_kernel(const float* __restrict__ w_def) {
    int idx = blockIdx.x * 256 + threadIdx.x;
    if (idx >= OUTC * Cin * 9) return;
    int o = idx / (Cin * 9);
    int rem = idx - o * (Cin * 9);
    int c = rem / 9;
    int k = rem - c * 9;
    g_wT[(k * Cin + c) * OUTC + o] = __uint_as_float(f32_to_tf32(w_def[idx]));
}

// ---------------------------------------------------------------------------
// Kernel 0b: transpose x NCHW -> NHWC (g_xt)
// ---------------------------------------------------------------------------
__global__ void __launch_bounds__(256) transpose_x_kernel(const float* __restrict__ x) {
    __shared__ float t[Cin][33];
    int tid = threadIdx.x;
    int bx = blockIdx.x;
    int wt = (bx & 7) << 5;
    int h = (bx >> 3) & (H - 1);
    int b = bx >> 11;

    const float* xb = x + (size_t)b * Cin * HW + h * W + wt;
#pragma unroll
    for (int it = 0; it < 8; it++) {
        int c = it * 8 + (tid >> 5);
        int w = tid & 31;
        t[c][w] = xb[(size_t)c * HW + w];
    }
    __syncthreads();
    float* xo = g_xt + ((size_t)(b * H + h) * W + wt) * Cin;
#pragma unroll
    for (int it = 0; it < 8; it++) {
        int w = it * 4 + (tid >> 6);
        int c = tid & 63;
        xo[(size_t)w * Cin + c] = t[c][w];
    }
}

// ---------------------------------------------------------------------------
// Kernel 1: offset conv (exact fp32, packed f32x2 FMA)
// acc pairs: (0,1)..(16,17) -> 9 x f32x2. Weight layout keeps j-pairs adjacent.
// ---------------------------------------------------------------------------
__global__ void __launch_bounds__(256) offsets_kernel(
    const float* __restrict__ x,
    const float* __restrict__ w_off,
    const float* __restrict__ b_off)
{
    __shared__ float wA[Cin * 9 * 20];   // [c*9+t][j(18) pad 20] — 8B aligned pairs

    int tid = threadIdx.x;
    for (int i = tid; i < Cin * 9 * 18; i += 256) {
        int j = i % 18;
        int ct = i / 18;
        wA[ct * 20 + j] = w_off[j * (Cin * 9) + ct];
    }
    for (int i = tid; i < Cin * 9; i += 256) {
        wA[i * 20 + 18] = 0.f;
        wA[i * 20 + 19] = 0.f;
    }
    __syncthreads();

    int w = tid;
    int h = blockIdx.x % H;
    int b = blockIdx.x / H;

    unsigned long long acc[9];
#pragma unroll
    for (int j = 0; j < 9; j++) {
        float2 bv = *(const float2*)&b_off[2 * j];
        asm("mov.b64 %0, {%1, %2};" : "=l"(acc[j]) : "f"(bv.x), "f"(bv.y));
    }

    const float* xb = x + (size_t)b * Cin * HW;
    bool hok[3] = { h > 0, true, h < H - 1 };
    bool wok[3] = { w > 0, true, w < W - 1 };

    for (int c = 0; c < Cin; c++) {
        const float* xc = xb + c * HW + h * W + w;
        float v[9];
#pragma unroll
        for (int dy = 0; dy < 3; dy++)
#pragma unroll
            for (int dx = 0; dx < 3; dx++) {
                int t = dy * 3 + dx;
                v[t] = (hok[dy] && wok[dx]) ? xc[(dy - 1) * W + (dx - 1)] : 0.f;
            }
#pragma unroll
        for (int t = 0; t < 9; t++) {
            unsigned long long vt2 = bcast2(v[t]);
            const unsigned long long* wp =
                (const unsigned long long*)&wA[(c * 9 + t) * 20];
#pragma unroll
            for (int j = 0; j < 9; j++) ffma2(acc[j], vt2, wp[j]);
        }
    }

    float* ob = g_offs + ((size_t)b * 18) * HW + h * W + w;
#pragma unroll
    for (int j = 0; j < 9; j++) {
        float lo, hi;
        unpack2(acc[j], lo, hi);
        ob[(size_t)(2 * j) * HW] = lo;
        ob[(size_t)(2 * j + 1) * HW] = hi;
    }
}

// ---------------------------------------------------------------------------
// Kernel 2: deform sampling (NHWC, coalesced) + tf32 tensor-core GEMM
// (unchanged from R3 — protected win)
// ---------------------------------------------------------------------------
struct __align__(16) SampleParam { int y0; int x0; float ly; float lx; };

#define SSM_U32 (MTILE * SSTRIDE)
#define WSM_U32 (Cin * WSTRIDE)
#define DSMEM_BYTES ((SSM_U32 + WSM_U32) * 4 + 9 * MTILE * 16)

__global__ void __launch_bounds__(256) deform_kernel(
    const float* __restrict__ b_def,
    float* __restrict__ out)
{
    extern __shared__ uint32_t dsm[];
    uint32_t* ssm = dsm;                        // [px][c] stride 68
    uint32_t* wsm = dsm + SSM_U32;              // [c][o]  stride 72
    SampleParam* sp = (SampleParam*)(dsm + SSM_U32 + WSM_U32);   // [k][px]

    int tid = threadIdx.x;
    int bx = blockIdx.x;
    int wt = (bx & 1) << 7;
    int h = (bx >> 1) & (H - 1);
    int b = bx >> 9;

    const float* offb = g_offs + (size_t)b * 18 * HW + h * W + wt;

    for (int i = tid; i < 9 * MTILE; i += 256) {
        int k = i >> 7;
        int px = i & (MTILE - 1);
        float offy = offb[(size_t)(2 * k) * HW + px];
        float offx = offb[(size_t)(2 * k + 1) * HW + px];
        float ys = (float)(h + (k / 3) - 1) + offy;
        float xs = (float)(wt + px + (k % 3) - 1) + offx;
        float y0f = floorf(ys);
        float x0f = floorf(xs);
        SampleParam p;
        p.y0 = (int)y0f;
        p.x0 = (int)x0f;
        p.ly = ys - y0f;
        p.lx = xs - x0f;
        sp[k * MTILE + px] = p;
    }

    int lane = tid & 31;
    int wid = tid >> 5;
    int warp_m = (wid & 3) << 5;
    int warp_n = (wid >> 2) << 5;
    int r = lane & 3;
    int g = lane >> 2;

    float acc[2][4][4];
#pragma unroll
    for (int mi = 0; mi < 2; mi++)
#pragma unroll
        for (int ni = 0; ni < 4; ni++)
#pragma unroll
            for (int q = 0; q < 4; q++) acc[mi][ni][q] = 0.f;

    const float2* xtb = (const float2*)(g_xt + (size_t)b * HW * Cin) + lane;
    int px0 = wid << 4;

    for (int k = 0; k < 9; k++) {
        __syncthreads();

        {
            const float4* src = (const float4*)(g_wT + (size_t)k * Cin * OUTC);
            for (int i = tid; i < Cin * OUTC / 4; i += 256) {
                int c = i >> 4;
                int q = i & 15;
                ((float4*)(wsm + c * WSTRIDE))[q] = src[i];
            }
        }

#pragma unroll 4
        for (int s = 0; s < 16; s++) {
            int px = px0 + s;
            SampleParam p = sp[k * MTILE + px];
            float hy = 1.f - p.ly, hx = 1.f - p.lx;
            float w00 = hy * hx, w01 = hy * p.lx;
            float w10 = p.ly * hx, w11 = p.ly * p.lx;
            bool y0k = ((unsigned)p.y0 < (unsigned)H);
            bool y1k = ((unsigned)(p.y0 + 1) < (unsigned)H);
            bool x0k = ((unsigned)p.x0 < (unsigned)W);
            bool x1k = ((unsigned)(p.x0 + 1) < (unsigned)W);
            const float2* base = xtb + (ptrdiff_t)(p.y0 * W + p.x0) * (Cin / 2);
            float2 z = make_float2(0.f, 0.f);
            float2 v00 = (y0k && x0k) ? base[0] : z;
            float2 v01 = (y0k && x1k) ? base[Cin / 2] : z;
            float2 v10 = (y1k && x0k) ? base[(ptrdiff_t)W * (Cin / 2)] : z;
            float2 v11 = (y1k && x1k) ? base[(ptrdiff_t)(W + 1) * (Cin / 2)] : z;
            float vx = w00 * v00.x + w01 * v01.x + w10 * v10.x + w11 * v11.x;
            float vy = w00 * v00.y + w01 * v01.y + w10 * v10.y + w11 * v11.y;
            uint2 tv = make_uint2(f32_to_tf32(vx), f32_to_tf32(vy));
            *(uint2*)&ssm[px * SSTRIDE + 2 * lane] = tv;
        }
        __syncthreads();

#pragma unroll
        for (int kk = 0; kk < 8; kk++) {
            int k0 = kk << 3;
            uint32_t a[2][4];
#pragma unroll
            for (int mi = 0; mi < 2; mi++) {
                const uint32_t* ar = ssm + (warp_m + 16 * mi + g) * SSTRIDE + k0 + r;
                a[mi][0] = ar[0];
                a[mi][1] = ar[8 * SSTRIDE];
                a[mi][2] = ar[4];
                a[mi][3] = ar[8 * SSTRIDE + 4];
            }
            uint32_t bb[4][2];
            const uint32_t* br = wsm + (k0 + r) * WSTRIDE + warp_n + g;
#pragma unroll
            for (int ni = 0; ni < 4; ni++) {
                bb[ni][0] = br[ni * 8];
                bb[ni][1] = br[ni * 8 + 4 * WSTRIDE];
            }
#pragma unroll
            for (int mi = 0; mi < 2; mi++)
#pragma unroll
                for (int ni = 0; ni < 4; ni++)
                    mma_tf32(acc[mi][ni], a[mi], bb[ni]);
        }
    }

#pragma unroll
    for (int ni = 0; ni < 4; ni++) {
        int o = warp_n + ni * 8 + 2 * r;
        float bo0 = b_def[o];
        float bo1 = b_def[o + 1];
        float* ob0 = out + ((size_t)(b * OUTC + o)) * HW + h * W + wt;
        float* ob1 = ob0 + HW;
#pragma unroll
        for (int mi = 0; mi < 2; mi++) {
            int px = warp_m + mi * 16 + g;
            ob0[px]     = acc[mi][ni][0] + bo0;
            ob1[px]     = acc[mi][ni][1] + bo1;
            ob0[px + 8] = acc[mi][ni][2] + bo0;
            ob1[px + 8] = acc[mi][ni][3] + bo1;
        }
    }
}

// ---------------------------------------------------------------------------
extern "C" void kernel_launch(void* const* d_in, const int* in_sizes, int n_in,
                              void* d_out, int out_size)
{
    const float* x     = (const float*)d_in[0];
    const float* w_off = (const float*)d_in[1];
    const float* b_off = (const float*)d_in[2];
    const float* w_def = (const float*)d_in[3];
    const float* b_def = (const float*)d_in[4];
    float* out = (float*)d_out;

    cudaFuncSetAttribute(deform_kernel,
                         cudaFuncAttributeMaxDynamicSharedMemorySize, DSMEM_BYTES);

    transpose_wdef_kernel<<<(OUTC * Cin * 9 + 255) / 256, 256>>>(w_def);
    transpose_x_kernel<<<Bsz * H * (W / 32), 256>>>(x);
    offsets_kernel<<<Bsz * H, 256>>>(x, w_off, b_off);
    deform_kernel<<<Bsz * H * (W / MTILE), 256, DSMEM_BYTES>>>(b_def, out);
}

// round 5
// speedup vs baseline: 1.8787x; 1.0719x over previous
#include <cuda_runtime.h>
#include <cstdint>

#define Bsz 4
#define Cin 64
#define OUTC 64
#define H 256
#define W 256
#define HW (H*W)

#define MTILE 128          // pixels per CTA (half row)
#define SSTRIDE 68         // ssm row stride in floats: [px][c], 64+4 pad
#define WSTRIDE 72         // wsm row stride: [c][o], 64+8 pad

// Scratch (device globals — no allocation allowed)
__device__ float g_offs[(size_t)Bsz * 18 * HW];        // offset conv output (fp32)
__device__ float g_wT[9 * Cin * OUTC];                 // w_def -> [k][c][o] (tf32 bits)
__device__ float g_xt[(size_t)Bsz * HW * Cin];         // x transposed to NHWC (64MB)

// ---------------------------------------------------------------------------
// tf32 / f32x2 helpers
// ---------------------------------------------------------------------------
__device__ __forceinline__ uint32_t f32_to_tf32(float v) {
    uint32_t t;
    asm("cvt.rna.tf32.f32 %0, %1;" : "=r"(t) : "f"(v));
    return t;
}

__device__ __forceinline__ void mma_tf32(float* d, const uint32_t* a, const uint32_t* b) {
    asm volatile(
        "mma.sync.aligned.m16n8k8.row.col.f32.tf32.tf32.f32 "
        "{%0,%1,%2,%3}, {%4,%5,%6,%7}, {%8,%9}, {%0,%1,%2,%3};"
        : "+f"(d[0]), "+f"(d[1]), "+f"(d[2]), "+f"(d[3])
        : "r"(a[0]), "r"(a[1]), "r"(a[2]), "r"(a[3]),
          "r"(b[0]), "r"(b[1]));
}

// packed dual-FMA: d = a*b + d (elementwise on 2 floats) — exact fp32
__device__ __forceinline__ void ffma2(unsigned long long& d,
                                      unsigned long long a,
                                      unsigned long long b) {
    asm("fma.rn.f32x2 %0, %1, %2, %0;" : "+l"(d) : "l"(a), "l"(b));
}

__device__ __forceinline__ unsigned long long bcast2(float v) {
    unsigned long long r;
    asm("mov.b64 %0, {%1, %1};" : "=l"(r) : "f"(v));
    return r;
}

__device__ __forceinline__ void unpack2(unsigned long long v, float& lo, float& hi) {
    asm("mov.b64 {%0, %1}, %2;" : "=f"(lo), "=f"(hi) : "l"(v));
}

// ---------------------------------------------------------------------------
// Kernel 0a: transpose w_def [o][c][ki][kj] -> g_wT[k][c][o], tf32-rounded
// ---------------------------------------------------------------------------
__global__ void transpose_wdef_kernel(const float* __restrict__ w_def) {
    int idx = blockIdx.x * 256 + threadIdx.x;
    if (idx >= OUTC * Cin * 9) return;
    int o = idx / (Cin * 9);
    int rem = idx - o * (Cin * 9);
    int c = rem / 9;
    int k = rem - c * 9;
    g_wT[(k * Cin + c) * OUTC + o] = __uint_as_float(f32_to_tf32(w_def[idx]));
}

// ---------------------------------------------------------------------------
// Kernel 0b: transpose x NCHW -> NHWC (g_xt)
// ---------------------------------------------------------------------------
__global__ void __launch_bounds__(256) transpose_x_kernel(const float* __restrict__ x) {
    __shared__ float t[Cin][33];
    int tid = threadIdx.x;
    int bx = blockIdx.x;
    int wt = (bx & 7) << 5;
    int h = (bx >> 3) & (H - 1);
    int b = bx >> 11;

    const float* xb = x + (size_t)b * Cin * HW + h * W + wt;
#pragma unroll
    for (int it = 0; it < 8; it++) {
        int c = it * 8 + (tid >> 5);
        int w = tid & 31;
        t[c][w] = xb[(size_t)c * HW + w];
    }
    __syncthreads();
    float* xo = g_xt + ((size_t)(b * H + h) * W + wt) * Cin;
#pragma unroll
    for (int it = 0; it < 8; it++) {
        int w = it * 4 + (tid >> 6);
        int c = tid & 63;
        xo[(size_t)w * Cin + c] = t[c][w];
    }
}

// ---------------------------------------------------------------------------
// Kernel 1: offset conv (exact fp32; FFMA2 with wide LDS.128 operand loads)
// ---------------------------------------------------------------------------
__global__ void __launch_bounds__(256) offsets_kernel(
    const float* __restrict__ x,
    const float* __restrict__ w_off,
    const float* __restrict__ b_off)
{
    __shared__ float wA[Cin * 9 * 20];   // [c*9+t][18 pad 20] — 16B-aligned rows

    int tid = threadIdx.x;
    for (int i = tid; i < Cin * 9 * 18; i += 256) {
        int j = i % 18;
        int ct = i / 18;
        wA[ct * 20 + j] = w_off[j * (Cin * 9) + ct];
    }
    for (int i = tid; i < Cin * 9; i += 256) {
        wA[i * 20 + 18] = 0.f;
        wA[i * 20 + 19] = 0.f;
    }
    __syncthreads();

    int w = tid;
    int h = blockIdx.x % H;
    int b = blockIdx.x / H;

    unsigned long long acc[9];
#pragma unroll
    for (int j = 0; j < 9; j++) {
        float2 bv = *(const float2*)&b_off[2 * j];
        asm("mov.b64 %0, {%1, %2};" : "=l"(acc[j]) : "f"(bv.x), "f"(bv.y));
    }

    const float* xb = x + (size_t)b * Cin * HW;
    bool hok[3] = { h > 0, true, h < H - 1 };
    bool wok[3] = { w > 0, true, w < W - 1 };

    for (int c = 0; c < Cin; c++) {
        const float* xc = xb + c * HW + h * W + w;
        float v[9];
#pragma unroll
        for (int dy = 0; dy < 3; dy++)
#pragma unroll
            for (int dx = 0; dx < 3; dx++) {
                int t = dy * 3 + dx;
                v[t] = (hok[dy] && wok[dx]) ? xc[(dy - 1) * W + (dx - 1)] : 0.f;
            }
#pragma unroll
        for (int t = 0; t < 9; t++) {
            unsigned long long vt2 = bcast2(v[t]);
            const float* wp = &wA[(c * 9 + t) * 20];
            ulonglong2 q0 = *(const ulonglong2*)(wp);        // j0..j3
            ulonglong2 q1 = *(const ulonglong2*)(wp + 4);    // j4..j7
            ulonglong2 q2 = *(const ulonglong2*)(wp + 8);    // j8..j11
            ulonglong2 q3 = *(const ulonglong2*)(wp + 12);   // j12..j15
            unsigned long long q4 = *(const unsigned long long*)(wp + 16); // j16,j17
            ffma2(acc[0], vt2, q0.x);
            ffma2(acc[1], vt2, q0.y);
            ffma2(acc[2], vt2, q1.x);
            ffma2(acc[3], vt2, q1.y);
            ffma2(acc[4], vt2, q2.x);
            ffma2(acc[5], vt2, q2.y);
            ffma2(acc[6], vt2, q3.x);
            ffma2(acc[7], vt2, q3.y);
            ffma2(acc[8], vt2, q4);
        }
    }

    float* ob = g_offs + ((size_t)b * 18) * HW + h * W + w;
#pragma unroll
    for (int j = 0; j < 9; j++) {
        float lo, hi;
        unpack2(acc[j], lo, hi);
        ob[(size_t)(2 * j) * HW] = lo;
        ob[(size_t)(2 * j + 1) * HW] = hi;
    }
}

// ---------------------------------------------------------------------------
// Kernel 2: deform sampling (NHWC) + tf32 MMA, 4 CTAs/SM via small sp buffer.
// sp holds ONE tap's params; tap k+1's params are computed during tap k's MMA
// phase (write after sync2, read after next sync1 — ordered, no extra barrier).
// ---------------------------------------------------------------------------
struct __align__(16) SampleParam { int y0; int x0; float ly; float lx; };

#define SSM_U32 (MTILE * SSTRIDE)
#define WSM_U32 (Cin * WSTRIDE)
#define DSMEM_BYTES ((SSM_U32 + WSM_U32) * 4 + MTILE * 16)   // 55296 B

__global__ void __launch_bounds__(256, 4) deform_kernel(
    const float* __restrict__ b_def,
    float* __restrict__ out)
{
    extern __shared__ uint32_t dsm[];
    uint32_t* ssm = dsm;                        // [px][c] stride 68
    uint32_t* wsm = dsm + SSM_U32;              // [c][o]  stride 72
    SampleParam* sp = (SampleParam*)(dsm + SSM_U32 + WSM_U32);   // [px], one tap

    int tid = threadIdx.x;
    int bx = blockIdx.x;
    int wt = (bx & 1) << 7;
    int h = (bx >> 1) & (H - 1);
    int b = bx >> 9;

    const float* offb = g_offs + (size_t)b * 18 * HW + h * W + wt;

    // params for tap 0 (covered by loop-top sync)
    if (tid < MTILE) {
        int px = tid;
        float offy = offb[0 * HW + px];
        float offx = offb[1 * HW + px];
        float ys = (float)(h - 1) + offy;
        float xs = (float)(wt + px - 1) + offx;
        float y0f = floorf(ys);
        float x0f = floorf(xs);
        SampleParam p;
        p.y0 = (int)y0f;
        p.x0 = (int)x0f;
        p.ly = ys - y0f;
        p.lx = xs - x0f;
        sp[px] = p;
    }

    int lane = tid & 31;
    int wid = tid >> 5;
    int warp_m = (wid & 3) << 5;
    int warp_n = (wid >> 2) << 5;
    int r = lane & 3;
    int g = lane >> 2;

    float acc[2][4][4];
#pragma unroll
    for (int mi = 0; mi < 2; mi++)
#pragma unroll
        for (int ni = 0; ni < 4; ni++)
#pragma unroll
            for (int q = 0; q < 4; q++) acc[mi][ni][q] = 0.f;

    const float2* xtb = (const float2*)(g_xt + (size_t)b * HW * Cin) + lane;
    int px0 = wid << 4;

    for (int k = 0; k < 9; k++) {
        __syncthreads();   // ssm/wsm reusable; sp (this tap) visible

        // stage tf32 weights for this tap
        {
            const float4* src = (const float4*)(g_wT + (size_t)k * Cin * OUTC);
            for (int i = tid; i < Cin * OUTC / 4; i += 256) {
                int c = i >> 4;
                int q = i & 15;
                ((float4*)(wsm + c * WSTRIDE))[q] = src[i];
            }
        }

        // coalesced bilinear sampling: warp covers 16 px, lane = 2 channels
#pragma unroll 4
        for (int s = 0; s < 16; s++) {
            int px = px0 + s;
            SampleParam p = sp[px];
            float hy = 1.f - p.ly, hx = 1.f - p.lx;
            float w00 = hy * hx, w01 = hy * p.lx;
            float w10 = p.ly * hx, w11 = p.ly * p.lx;
            bool y0k = ((unsigned)p.y0 < (unsigned)H);
            bool y1k = ((unsigned)(p.y0 + 1) < (unsigned)H);
            bool x0k = ((unsigned)p.x0 < (unsigned)W);
            bool x1k = ((unsigned)(p.x0 + 1) < (unsigned)W);
            const float2* base = xtb + (ptrdiff_t)(p.y0 * W + p.x0) * (Cin / 2);
            float2 z = make_float2(0.f, 0.f);
            float2 v00 = (y0k && x0k) ? base[0] : z;
            float2 v01 = (y0k && x1k) ? base[Cin / 2] : z;
            float2 v10 = (y1k && x0k) ? base[(ptrdiff_t)W * (Cin / 2)] : z;
            float2 v11 = (y1k && x1k) ? base[(ptrdiff_t)(W + 1) * (Cin / 2)] : z;
            float vx = w00 * v00.x + w01 * v01.x + w10 * v10.x + w11 * v11.x;
            float vy = w00 * v00.y + w01 * v01.y + w10 * v10.y + w11 * v11.y;
            uint2 tv = make_uint2(f32_to_tf32(vx), f32_to_tf32(vy));
            *(uint2*)&ssm[px * SSTRIDE + 2 * lane] = tv;
        }
        __syncthreads();   // ssm ready; sp readers (this tap) done

        // prefetch next tap's sampling params (overlaps MMA)
        if (k < 8 && tid < MTILE) {
            int kn = k + 1;
            int px = tid;
            float offy = offb[(size_t)(2 * kn) * HW + px];
            float offx = offb[(size_t)(2 * kn + 1) * HW + px];
            float ys = (float)(h + (kn / 3) - 1) + offy;
            float xs = (float)(wt + px + (kn % 3) - 1) + offx;
            float y0f = floorf(ys);
            float x0f = floorf(xs);
            SampleParam p;
            p.y0 = (int)y0f;
            p.x0 = (int)x0f;
            p.ly = ys - y0f;
            p.lx = xs - x0f;
            sp[px] = p;
        }

        // MMA: 8 k-steps of m16n8k8
#pragma unroll
        for (int kk = 0; kk < 8; kk++) {
            int k0 = kk << 3;
            uint32_t a[2][4];
#pragma unroll
            for (int mi = 0; mi < 2; mi++) {
                const uint32_t* ar = ssm + (warp_m + 16 * mi + g) * SSTRIDE + k0 + r;
                a[mi][0] = ar[0];
                a[mi][1] = ar[8 * SSTRIDE];
                a[mi][2] = ar[4];
                a[mi][3] = ar[8 * SSTRIDE + 4];
            }
            uint32_t bb[4][2];
            const uint32_t* br = wsm + (k0 + r) * WSTRIDE + warp_n + g;
#pragma unroll
            for (int ni = 0; ni < 4; ni++) {
                bb[ni][0] = br[ni * 8];
                bb[ni][1] = br[ni * 8 + 4 * WSTRIDE];
            }
#pragma unroll
            for (int mi = 0; mi < 2; mi++)
#pragma unroll
                for (int ni = 0; ni < 4; ni++)
                    mma_tf32(acc[mi][ni], a[mi], bb[ni]);
        }
    }

    // ---- epilogue: bias + direct stores (NCHW out) ----
#pragma unroll
    for (int ni = 0; ni < 4; ni++) {
        int o = warp_n + ni * 8 + 2 * r;
        float bo0 = b_def[o];
        float bo1 = b_def[o + 1];
        float* ob0 = out + ((size_t)(b * OUTC + o)) * HW + h * W + wt;
        float* ob1 = ob0 + HW;
#pragma unroll
        for (int mi = 0; mi < 2; mi++) {
            int px = warp_m + mi * 16 + g;
            ob0[px]     = acc[mi][ni][0] + bo0;
            ob1[px]     = acc[mi][ni][1] + bo1;
            ob0[px + 8] = acc[mi][ni][2] + bo0;
            ob1[px + 8] = acc[mi][ni][3] + bo1;
        }
    }
}

// ---------------------------------------------------------------------------
extern "C" void kernel_launch(void* const* d_in, const int* in_sizes, int n_in,
                              void* d_out, int out_size)
{
    const float* x     = (const float*)d_in[0];
    const float* w_off = (const float*)d_in[1];
    const float* b_off = (const float*)d_in[2];
    const float* w_def = (const float*)d_in[3];
    const float* b_def = (const float*)d_in[4];
    float* out = (float*)d_out;

    cudaFuncSetAttribute(deform_kernel,
                         cudaFuncAttributeMaxDynamicSharedMemorySize, DSMEM_BYTES);

    transpose_wdef_kernel<<<(OUTC * Cin * 9 + 255) / 256, 256>>>(w_def);
    transpose_x_kernel<<<Bsz * H * (W / 32), 256>>>(x);
    offsets_kernel<<<Bsz * H, 256>>>(x, w_off, b_off);
    deform_kernel<<<Bsz * H * (W / MTILE), 256, DSMEM_BYTES>>>(b_def, out);
}